// round 1
// baseline (speedup 1.0000x reference)
#include <cuda_runtime.h>

// y[b, n] = sum_k x[b,k] * W[n,k] + bias[n]
// B = 512 (rows of x), K = 512, N = 512, all fp32.
// The LNS reference is mathematically equivalent to this matmul; fp32 FFMA
// accumulation is within ~1e-6 of it (budget is 1e-3).

constexpr int KDIM = 512;
constexpr int NDIM = 512;
constexpr int BDIM = 512;

constexpr int BM = 32;   // rows of x per CTA
constexpr int BN = 64;   // cols (rows of W) per CTA
constexpr int BK = 32;   // k-slice per stage
constexpr int NTHREADS = 256;

__global__ __launch_bounds__(NTHREADS, 1)
void lns_linear_kernel(const float* __restrict__ X,
                       const float* __restrict__ W,
                       const float* __restrict__ bias,
                       float* __restrict__ Y)
{
    // smem tiles stored k-major (transposed) for conflict-light inner loop.
    __shared__ float As[BK][BM + 2];   // stride 34 floats (136B, 8B aligned)
    __shared__ float Bs[BK][BN + 4];   // stride 68 floats (272B, 16B aligned)

    const int tid = threadIdx.x;
    const int tx = tid & 15;      // n-dim thread coord (16)
    const int ty = tid >> 4;      // m-dim thread coord (16)
    const int block_m = blockIdx.y * BM;
    const int block_n = blockIdx.x * BN;

    // Global-load mapping: each row of a tile is 32 k-values = 8 float4s.
    const int g_row = tid >> 3;          // 0..31
    const int g_kc  = (tid & 7) << 2;    // 0,4,...,28

    const float* Aptr  = X + (block_m + g_row)      * KDIM + g_kc;
    const float* Bptr0 = W + (block_n + g_row)      * KDIM + g_kc;  // W rows 0..31 of tile
    const float* Bptr1 = W + (block_n + 32 + g_row) * KDIM + g_kc;  // W rows 32..63 of tile

    // Prefetch stage 0 into registers.
    float4 pa  = *reinterpret_cast<const float4*>(Aptr);
    float4 pb0 = *reinterpret_cast<const float4*>(Bptr0);
    float4 pb1 = *reinterpret_cast<const float4*>(Bptr1);

    float acc[2][4] = {};

    constexpr int KTILES = KDIM / BK;   // 16
    for (int kt = 0; kt < KTILES; ++kt) {
        // Commit prefetched tile to smem (transposed: [k][m] / [k][n]).
        As[g_kc + 0][g_row] = pa.x;
        As[g_kc + 1][g_row] = pa.y;
        As[g_kc + 2][g_row] = pa.z;
        As[g_kc + 3][g_row] = pa.w;

        Bs[g_kc + 0][g_row] = pb0.x;
        Bs[g_kc + 1][g_row] = pb0.y;
        Bs[g_kc + 2][g_row] = pb0.z;
        Bs[g_kc + 3][g_row] = pb0.w;

        Bs[g_kc + 0][32 + g_row] = pb1.x;
        Bs[g_kc + 1][32 + g_row] = pb1.y;
        Bs[g_kc + 2][32 + g_row] = pb1.z;
        Bs[g_kc + 3][32 + g_row] = pb1.w;

        __syncthreads();

        // Issue next stage's global loads before compute (latency hidden
        // behind the 32-step FFMA loop; after tile 0 these are L2 hits).
        if (kt + 1 < KTILES) {
            const int off = (kt + 1) * BK;
            pa  = *reinterpret_cast<const float4*>(Aptr  + off);
            pb0 = *reinterpret_cast<const float4*>(Bptr0 + off);
            pb1 = *reinterpret_cast<const float4*>(Bptr1 + off);
        }

        const int m_off = ty * 2;
        const int n_off = tx * 4;
        #pragma unroll
        for (int k = 0; k < BK; ++k) {
            float a0 = As[k][m_off + 0];
            float a1 = As[k][m_off + 1];
            float4 b = *reinterpret_cast<const float4*>(&Bs[k][n_off]);
            acc[0][0] += a0 * b.x;
            acc[0][1] += a0 * b.y;
            acc[0][2] += a0 * b.z;
            acc[0][3] += a0 * b.w;
            acc[1][0] += a1 * b.x;
            acc[1][1] += a1 * b.y;
            acc[1][2] += a1 * b.z;
            acc[1][3] += a1 * b.w;
        }

        __syncthreads();
    }

    // Epilogue: add bias, vectorized store.
    const int m0 = block_m + ty * 2;
    const int n0 = block_n + tx * 4;
    float4 bv = *reinterpret_cast<const float4*>(&bias[n0]);

    #pragma unroll
    for (int i = 0; i < 2; ++i) {
        float4 o;
        o.x = acc[i][0] + bv.x;
        o.y = acc[i][1] + bv.y;
        o.z = acc[i][2] + bv.z;
        o.w = acc[i][3] + bv.w;
        *reinterpret_cast<float4*>(&Y[(m0 + i) * NDIM + n0]) = o;
    }
}

extern "C" void kernel_launch(void* const* d_in, const int* in_sizes, int n_in,
                              void* d_out, int out_size)
{
    const float* x    = (const float*)d_in[0];   // [512, 512]
    const float* w    = (const float*)d_in[1];   // [512, 512] (N, K)
    const float* bias = (const float*)d_in[2];   // [512]
    float* y = (float*)d_out;                    // [512, 512]

    dim3 grid(NDIM / BN, BDIM / BM);             // (8, 16) = 128 CTAs
    lns_linear_kernel<<<grid, NTHREADS>>>(x, w, bias, y);
}

// round 4
// speedup vs baseline: 2.2604x; 2.2604x over previous
#include <cuda_runtime.h>
#include <cuda_bf16.h>
#include <cstdint>

// y = x @ W^T + bias, B=K=N=512 fp32. LNS reference == plain fp32 matmul.
// bf16 hi/lo split (3 HMMA terms) via mma.sync.m16n8k16, fp32 accumulate.
// (tcgen05 is unusable: harness compiles PTX at compute_103, which gates
//  all sm_103a-only features. mma.sync/ldmatrix are plain sm_80 PTX.)

constexpr int KDIM = 512;
constexpr int NDIM = 512;
constexpr int BDIM = 512;

constexpr int BM = 64;    // x rows per CTA
constexpr int BN = 32;    // W rows per CTA
constexpr int KC = 64;    // k per stage
constexpr int NCHUNK = KDIM / KC;   // 8
constexpr int NTH = 256;

// smem: bf16 tiles with padded row stride 72 elems (144B) for conflict-free
// ldmatrix (36 words/row; 36 mod 32 = 4 -> 8 rows cover all 32 banks).
constexpr int LDS_B = 144;                    // row stride bytes
constexpr int AH_OFF = 0;
constexpr int AL_OFF = BM * LDS_B;            //  9216
constexpr int BH_OFF = 2 * BM * LDS_B;        // 18432
constexpr int BL_OFF = BH_OFF + BN * LDS_B;   // 23040
constexpr int STAGE  = BH_OFF + 2 * BN * LDS_B;  // 27648
constexpr int SMEM_TOTAL = 2 * STAGE;            // 55296

__device__ __forceinline__ uint32_t smem_u32(const void* p) {
    uint32_t a;
    asm("{ .reg .u64 t; cvta.to.shared.u64 t, %1; cvt.u32.u64 %0, t; }"
        : "=r"(a) : "l"(p));
    return a;
}

__device__ __forceinline__ void ldsm_x4(uint32_t& r0, uint32_t& r1,
                                        uint32_t& r2, uint32_t& r3, uint32_t addr) {
    asm volatile("ldmatrix.sync.aligned.m8n8.x4.shared.b16 {%0,%1,%2,%3}, [%4];"
                 : "=r"(r0), "=r"(r1), "=r"(r2), "=r"(r3) : "r"(addr));
}

__device__ __forceinline__ void mma16816(float* c, const uint32_t* a,
                                         uint32_t b0, uint32_t b1) {
    asm volatile(
        "mma.sync.aligned.m16n8k16.row.col.f32.bf16.bf16.f32 "
        "{%0,%1,%2,%3}, {%4,%5,%6,%7}, {%8,%9}, {%0,%1,%2,%3};"
        : "+f"(c[0]), "+f"(c[1]), "+f"(c[2]), "+f"(c[3])
        : "r"(a[0]), "r"(a[1]), "r"(a[2]), "r"(a[3]), "r"(b0), "r"(b1));
}

// float4 -> 4 bf16 hi (uint2) + 4 bf16 lo (uint2), stored to smem.
__device__ __forceinline__ void cvt_store(char* smem, uint32_t hi_byte,
                                          uint32_t lo_byte, float4 v) {
    __nv_bfloat16 hx = __float2bfloat16_rn(v.x);
    __nv_bfloat16 hy = __float2bfloat16_rn(v.y);
    __nv_bfloat16 hz = __float2bfloat16_rn(v.z);
    __nv_bfloat16 hw = __float2bfloat16_rn(v.w);
    __nv_bfloat16 lx = __float2bfloat16_rn(v.x - __bfloat162float(hx));
    __nv_bfloat16 ly = __float2bfloat16_rn(v.y - __bfloat162float(hy));
    __nv_bfloat16 lz = __float2bfloat16_rn(v.z - __bfloat162float(hz));
    __nv_bfloat16 lw = __float2bfloat16_rn(v.w - __bfloat162float(hw));
    __nv_bfloat162 h0; h0.x = hx; h0.y = hy;
    __nv_bfloat162 h1; h1.x = hz; h1.y = hw;
    __nv_bfloat162 l0; l0.x = lx; l0.y = ly;
    __nv_bfloat162 l1; l1.x = lz; l1.y = lw;
    *reinterpret_cast<uint2*>(smem + hi_byte) =
        make_uint2(*reinterpret_cast<uint32_t*>(&h0), *reinterpret_cast<uint32_t*>(&h1));
    *reinterpret_cast<uint2*>(smem + lo_byte) =
        make_uint2(*reinterpret_cast<uint32_t*>(&l0), *reinterpret_cast<uint32_t*>(&l1));
}

__global__ __launch_bounds__(NTH, 1)
void lns_linear_hmma_kernel(const float* __restrict__ X,
                            const float* __restrict__ W,
                            const float* __restrict__ bias,
                            float* __restrict__ Y)
{
    extern __shared__ char smem[];
    const uint32_t sb = smem_u32(smem);
    const int tid = threadIdx.x;
    const int wid = tid >> 5;
    const int lid = tid & 31;
    const int wm = wid >> 1;          // 0..3 (m dir)
    const int wn = wid & 1;           // 0..1 (n dir)
    const int block_m = blockIdx.y * BM;
    const int block_n = blockIdx.x * BN;

    // ---- producer mapping ----
    // A: 64 rows x 16 float4/row; thread covers row (tid>>2), 4 float4s.
    const int a_row = tid >> 2;
    const int a_c   = tid & 3;                     // float4 slot 0..3 (stride 4)
    const float* Aptr = X + (block_m + a_row) * KDIM + a_c * 4;
    const uint32_t a_st = (uint32_t)(a_row * LDS_B + a_c * 8);   // +32B per r

    // B: 32 rows x 16 float4/row; thread covers row (tid>>3), 2 float4s.
    const int b_row = tid >> 3;
    const int b_c   = tid & 7;                     // float4 slot 0..7 (stride 8)
    const float* Bptr = W + (block_n + b_row) * KDIM + b_c * 4;
    const uint32_t b_st = (uint32_t)(b_row * LDS_B + b_c * 8);   // +64B per r

    // ---- ldmatrix lane addressing (byte offsets within a tile) ----
    // A m16k16: lanes 0-15 rows 0-15 (k bytes 0), lanes 16-31 same rows +16B.
    const uint32_t a_ld = (uint32_t)((wm * 16 + (lid & 15)) * LDS_B + (lid >> 4) * 16);
    // B n16k16: lane groups (0-7,8-15,16-23,24-31) -> (n0-7 k0, n0-7 k8, n8-15 k0, n8-15 k8)
    const uint32_t b_ld = (uint32_t)((wn * 16 + ((lid & 7) | ((lid >> 4) << 3))) * LDS_B
                                     + (((lid >> 3) & 1) * 16));

    float c0[4] = {};   // n8 block 0
    float c1[4] = {};   // n8 block 1

    // prefetch chunk 0
    float4 pa[4], pb[2];
    #pragma unroll
    for (int r = 0; r < 4; ++r) pa[r] = *reinterpret_cast<const float4*>(Aptr + r * 16);
    #pragma unroll
    for (int r = 0; r < 2; ++r) pb[r] = *reinterpret_cast<const float4*>(Bptr + r * 32);

    for (int chunk = 0; chunk < NCHUNK; ++chunk) {
        char* buf = smem + (chunk & 1) * STAGE;
        const uint32_t bufb = sb + (chunk & 1) * STAGE;

        // store prefetched chunk
        #pragma unroll
        for (int r = 0; r < 4; ++r)
            cvt_store(buf, AH_OFF + a_st + r * 32, AL_OFF + a_st + r * 32, pa[r]);
        #pragma unroll
        for (int r = 0; r < 2; ++r)
            cvt_store(buf, BH_OFF + b_st + r * 64, BL_OFF + b_st + r * 64, pb[r]);
        __syncthreads();

        // prefetch next chunk
        if (chunk + 1 < NCHUNK) {
            const int off = (chunk + 1) * KC;
            #pragma unroll
            for (int r = 0; r < 4; ++r)
                pa[r] = *reinterpret_cast<const float4*>(Aptr + off + r * 16);
            #pragma unroll
            for (int r = 0; r < 2; ++r)
                pb[r] = *reinterpret_cast<const float4*>(Bptr + off + r * 32);
        }

        // compute: 4 k16 steps
        #pragma unroll
        for (int s = 0; s < 4; ++s) {
            uint32_t ah[4], al[4], bh[4], bl[4];
            ldsm_x4(ah[0], ah[1], ah[2], ah[3], bufb + AH_OFF + a_ld + s * 32);
            ldsm_x4(al[0], al[1], al[2], al[3], bufb + AL_OFF + a_ld + s * 32);
            ldsm_x4(bh[0], bh[1], bh[2], bh[3], bufb + BH_OFF + b_ld + s * 32);
            ldsm_x4(bl[0], bl[1], bl[2], bl[3], bufb + BL_OFF + b_ld + s * 32);

            mma16816(c0, ah, bh[0], bh[1]);   // hi*hi
            mma16816(c1, ah, bh[2], bh[3]);
            mma16816(c0, ah, bl[0], bl[1]);   // hi*lo
            mma16816(c1, ah, bl[2], bl[3]);
            mma16816(c0, al, bh[0], bh[1]);   // lo*hi
            mma16816(c1, al, bh[2], bh[3]);
        }
        __syncthreads();
    }

    // ---- epilogue: c frag -> global, + bias ----
    // c layout: c[0],c[1]: row=lid/4, cols 2*(lid%4)+{0,1}; c[2],c[3]: row+8.
    const int row0 = block_m + wm * 16 + (lid >> 2);
    const int coln = block_n + wn * 16 + 2 * (lid & 3);

    #pragma unroll
    for (int j = 0; j < 2; ++j) {          // n8 block
        const float* cc = j ? c1 : c0;
        const int n = coln + j * 8;
        float2 bv = *reinterpret_cast<const float2*>(bias + n);
        float2 o0 = make_float2(cc[0] + bv.x, cc[1] + bv.y);
        float2 o1 = make_float2(cc[2] + bv.x, cc[3] + bv.y);
        *reinterpret_cast<float2*>(Y + (row0)     * NDIM + n) = o0;
        *reinterpret_cast<float2*>(Y + (row0 + 8) * NDIM + n) = o1;
    }
}

extern "C" void kernel_launch(void* const* d_in, const int* in_sizes, int n_in,
                              void* d_out, int out_size)
{
    const float* x    = (const float*)d_in[0];   // [512, 512]
    const float* w    = (const float*)d_in[1];   // [512, 512] (N, K)
    const float* bias = (const float*)d_in[2];   // [512]
    float* y = (float*)d_out;                    // [512, 512]

    cudaFuncSetAttribute(lns_linear_hmma_kernel,
                         cudaFuncAttributeMaxDynamicSharedMemorySize, SMEM_TOTAL);

    dim3 grid(NDIM / BN, BDIM / BM);             // (16, 8) = 128 CTAs, one wave
    lns_linear_hmma_kernel<<<grid, NTH, SMEM_TOTAL>>>(x, w, bias, y);
}

// round 6
// speedup vs baseline: 2.6901x; 1.1901x over previous
#include <cuda_runtime.h>
#include <cuda_bf16.h>
#include <cstdint>

// y = x @ W^T + bias, B=K=N=512 fp32.  LNS reference == plain fp32 matmul.
// Two kernels:
//  1) cvt_kernel: X,W f32 -> bf16 hi/lo pairs in __device__ scratch (once).
//  2) gemm_kernel: 3-term HMMA (xh*wh + xh*wl + xl*wh), fp32 accum,
//     cp.async 3-stage pipeline, no conversion in the hot loop.

constexpr int KDIM = 512;
constexpr int NDIM = 512;
constexpr int BDIM = 512;

// ---- scratch (static device memory; no allocation) ----
__device__ __nv_bfloat16 g_xh[BDIM * KDIM];
__device__ __nv_bfloat16 g_xl[BDIM * KDIM];
__device__ __nv_bfloat16 g_wh[NDIM * KDIM];
__device__ __nv_bfloat16 g_wl[NDIM * KDIM];

// ======================= convert kernel =======================
__global__ __launch_bounds__(256, 8)
void cvt_kernel(const float4* __restrict__ X, const float4* __restrict__ W)
{
    const int i = blockIdx.x * 256 + threadIdx.x;          // float4 index
    const float4* src = blockIdx.y ? W : X;
    uint2* dh = reinterpret_cast<uint2*>(blockIdx.y ? g_wh : g_xh);
    uint2* dl = reinterpret_cast<uint2*>(blockIdx.y ? g_wl : g_xl);

    float4 v = src[i];
    __nv_bfloat162 h0 = __floats2bfloat162_rn(v.x, v.y);
    __nv_bfloat162 h1 = __floats2bfloat162_rn(v.z, v.w);
    __nv_bfloat162 l0 = __floats2bfloat162_rn(v.x - __bfloat162float(h0.x),
                                              v.y - __bfloat162float(h0.y));
    __nv_bfloat162 l1 = __floats2bfloat162_rn(v.z - __bfloat162float(h1.x),
                                              v.w - __bfloat162float(h1.y));
    dh[i] = make_uint2(*reinterpret_cast<uint32_t*>(&h0),
                       *reinterpret_cast<uint32_t*>(&h1));
    dl[i] = make_uint2(*reinterpret_cast<uint32_t*>(&l0),
                       *reinterpret_cast<uint32_t*>(&l1));
}

// ======================= GEMM kernel =======================
constexpr int BM = 64;
constexpr int BN = 32;
constexpr int KC = 128;                  // k per chunk (bf16)
constexpr int NCHUNK = KDIM / KC;        // 4
constexpr int NSTAGE = 3;
constexpr int NTH = 256;

// smem tile row stride: 128 bf16 = 256B data + 16B pad = 272B
// (68 words; 68 mod 32 = 4 -> 8 consecutive rows hit distinct bank quads)
constexpr int ROWB = 272;
constexpr int AH_OFF = 0;
constexpr int AL_OFF = BM * ROWB;             // 17408
constexpr int BH_OFF = 2 * BM * ROWB;         // 34816
constexpr int BL_OFF = BH_OFF + BN * ROWB;    // 43520
constexpr int STAGE  = BH_OFF + 2 * BN * ROWB;    // 52224
constexpr int SMEM_TOTAL = NSTAGE * STAGE;        // 156672

__device__ __forceinline__ uint32_t smem_u32(const void* p) {
    uint32_t a;
    asm("{ .reg .u64 t; cvta.to.shared.u64 t, %1; cvt.u32.u64 %0, t; }"
        : "=r"(a) : "l"(p));
    return a;
}

__device__ __forceinline__ void cp16(uint32_t dst, const void* src) {
    asm volatile("cp.async.cg.shared.global [%0], [%1], 16;"
                 :: "r"(dst), "l"(src) : "memory");
}

__device__ __forceinline__ void ldsm_x4(uint32_t& r0, uint32_t& r1,
                                        uint32_t& r2, uint32_t& r3, uint32_t addr) {
    asm volatile("ldmatrix.sync.aligned.m8n8.x4.shared.b16 {%0,%1,%2,%3}, [%4];"
                 : "=r"(r0), "=r"(r1), "=r"(r2), "=r"(r3) : "r"(addr));
}

__device__ __forceinline__ void mma16816(float* c, const uint32_t* a,
                                         uint32_t b0, uint32_t b1) {
    asm volatile(
        "mma.sync.aligned.m16n8k16.row.col.f32.bf16.bf16.f32 "
        "{%0,%1,%2,%3}, {%4,%5,%6,%7}, {%8,%9}, {%0,%1,%2,%3};"
        : "+f"(c[0]), "+f"(c[1]), "+f"(c[2]), "+f"(c[3])
        : "r"(a[0]), "r"(a[1]), "r"(a[2]), "r"(a[3]), "r"(b0), "r"(b1));
}

__global__ __launch_bounds__(NTH, 1)
void gemm_kernel(const float* __restrict__ bias, float* __restrict__ Y)
{
    extern __shared__ char smem[];
    const uint32_t sb = smem_u32(smem);
    const int tid = threadIdx.x;
    const int wid = tid >> 5;
    const int lid = tid & 31;
    const int wm = wid >> 1;              // 0..3
    const int wn = wid & 1;               // 0..1
    const int block_m = blockIdx.y * BM;
    const int block_n = blockIdx.x * BN;

    // producer mapping: transfer idx -> (row, 16B-col)
    const int p_row = tid >> 4;           // 0..15 (+16 per iter)
    const int p_c   = tid & 15;           // 16B column 0..15

    const __nv_bfloat16* xh = g_xh + (block_m + p_row) * KDIM + p_c * 8;
    const __nv_bfloat16* xl = g_xl + (block_m + p_row) * KDIM + p_c * 8;
    const __nv_bfloat16* wh = g_wh + (block_n + p_row) * KDIM + p_c * 8;
    const __nv_bfloat16* wl = g_wl + (block_n + p_row) * KDIM + p_c * 8;
    const uint32_t p_st = (uint32_t)(p_row * ROWB + p_c * 16);

    // ldmatrix lane addressing (byte offsets within tile)
    const uint32_t a_ld = (uint32_t)((wm * 16 + (lid & 15)) * ROWB + (lid >> 4) * 16);
    const uint32_t b_ld = (uint32_t)((wn * 16 + ((lid & 7) | ((lid >> 4) << 3))) * ROWB
                                     + (((lid >> 3) & 1) * 16));

    float c0[4] = {};
    float c1[4] = {};

    auto issue = [&](int chunk) {
        const uint32_t st = sb + (chunk % NSTAGE) * STAGE;
        const int kb = chunk * KC;
        #pragma unroll
        for (int r = 0; r < 4; ++r) {       // A: 64 rows x 16 transfers
            const int ro = r * 16;
            cp16(st + AH_OFF + p_st + ro * ROWB, xh + kb + ro * KDIM);
            cp16(st + AL_OFF + p_st + ro * ROWB, xl + kb + ro * KDIM);
        }
        #pragma unroll
        for (int r = 0; r < 2; ++r) {       // B: 32 rows x 16 transfers
            const int ro = r * 16;
            cp16(st + BH_OFF + p_st + ro * ROWB, wh + kb + ro * KDIM);
            cp16(st + BL_OFF + p_st + ro * ROWB, wl + kb + ro * KDIM);
        }
        asm volatile("cp.async.commit_group;" ::: "memory");
    };

    issue(0);

    for (int i = 0; i < NCHUNK; ++i) {
        if (i + 1 < NCHUNK) {
            issue(i + 1);
            asm volatile("cp.async.wait_group 1;" ::: "memory");
        } else {
            asm volatile("cp.async.wait_group 0;" ::: "memory");
        }
        __syncthreads();

        const uint32_t st = sb + (i % NSTAGE) * STAGE;
        #pragma unroll
        for (int s = 0; s < KC / 16; ++s) {
            uint32_t ah[4], al[4], bh[4], bl[4];
            ldsm_x4(ah[0], ah[1], ah[2], ah[3], st + AH_OFF + a_ld + s * 32);
            ldsm_x4(al[0], al[1], al[2], al[3], st + AL_OFF + a_ld + s * 32);
            ldsm_x4(bh[0], bh[1], bh[2], bh[3], st + BH_OFF + b_ld + s * 32);
            ldsm_x4(bl[0], bl[1], bl[2], bl[3], st + BL_OFF + b_ld + s * 32);

            mma16816(c0, ah, bh[0], bh[1]);   // hi*hi
            mma16816(c1, ah, bh[2], bh[3]);
            mma16816(c0, ah, bl[0], bl[1]);   // hi*lo
            mma16816(c1, ah, bl[2], bl[3]);
            mma16816(c0, al, bh[0], bh[1]);   // lo*hi
            mma16816(c1, al, bh[2], bh[3]);
        }
        // no trailing sync: 3-stage ring means the buffer written by the next
        // issue() was last read two chunks ago, already fenced by the sync above.
    }

    // epilogue: add bias, store
    const int row0 = block_m + wm * 16 + (lid >> 2);
    const int coln = block_n + wn * 16 + 2 * (lid & 3);
    #pragma unroll
    for (int j = 0; j < 2; ++j) {
        const float* cc = j ? c1 : c0;
        const int n = coln + j * 8;
        float2 bv = *reinterpret_cast<const float2*>(bias + n);
        *reinterpret_cast<float2*>(Y + row0 * NDIM + n) =
            make_float2(cc[0] + bv.x, cc[1] + bv.y);
        *reinterpret_cast<float2*>(Y + (row0 + 8) * NDIM + n) =
            make_float2(cc[2] + bv.x, cc[3] + bv.y);
    }
}

extern "C" void kernel_launch(void* const* d_in, const int* in_sizes, int n_in,
                              void* d_out, int out_size)
{
    const float* x    = (const float*)d_in[0];   // [512, 512]
    const float* w    = (const float*)d_in[1];   // [512, 512] (N, K)
    const float* bias = (const float*)d_in[2];   // [512]
    float* y = (float*)d_out;                    // [512, 512]

    cvt_kernel<<<dim3(KDIM * BDIM / 4 / 256, 2), 256>>>(
        (const float4*)x, (const float4*)w);

    cudaFuncSetAttribute(gemm_kernel,
                         cudaFuncAttributeMaxDynamicSharedMemorySize, SMEM_TOTAL);
    dim3 grid(NDIM / BN, BDIM / BM);             // (16, 8) = 128 CTAs, one wave
    gemm_kernel<<<grid, NTH, SMEM_TOTAL>>>(bias, y);
}